// round 5
// baseline (speedup 1.0000x reference)
#include <cuda_runtime.h>
#include <cuda_bf16.h>

// Problem constants
#define kT   32768
#define kL   3
#define kCLS 1024

// Scratch (no cudaMalloc allowed) — device globals
__device__ float g_outs[kT];      // top-layer hidden states
__device__ float g_logits[kCLS];  // pre-softmax logits

// Hardware MUFU.TANH — measured (R2/R3) to contribute <1e-6 rel err over the
// full 32768-step recurrence.
__device__ __forceinline__ float fast_tanh(float x) {
    float y; asm("tanh.approx.f32 %0, %1;" : "=f"(y) : "f"(x)); return y;
}

// ---------------------------------------------------------------------------
// LSTM wavefront kernel: 1 warp. Lane l (l<3) runs layer l at timestep
// t = iter - 2*l (lag-2 pipeline: the 26-cycle SHFL cross-layer edge gets a
// full iteration of slack and never binds the recurrence cycle).
//
// Steady-state recurrence is re-parameterized around thc = tanh(c):
//   u_k   = Bog_k * thc + pre_k          (Bog_k = B_k * og_prev, folded)
//   th_k  = tanh(u_k)                    (issue order th0, th2, th1, th3)
//   ig    = 0.5*th0 + 0.5
//   cn    = th1*hc + (hc + ig*th2)       (hc = 0.5*c, off-path)
//   thc'  = tanh(cn)                     (5th MUFU, issues ~+45)
//   Bog_k'= th3*(0.5Bk) + (0.5Bk)        (in thc' latency shadow)
//   h     = og * thc'                    (off-cycle: only for shfl/store)
// This keeps the in-order MUFU schedule tight: dep period ~61-65 cyc/step.
// ---------------------------------------------------------------------------
__global__ void __launch_bounds__(32, 1)
lstm_kernel(const float* __restrict__ x,
            const float* __restrict__ h0,
            const float* __restrict__ c0,
            const float* __restrict__ w_ih,
            const float* __restrict__ w_hh,
            const float* __restrict__ b_ih,
            const float* __restrict__ b_hh)
{
    const int lane = threadIdx.x & 31;
    const int ll   = (lane < kL) ? lane : (kL - 1);

    const float bb0 = b_ih[ll*4+0] + b_hh[ll*4+0];
    const float bb1 = b_ih[ll*4+1] + b_hh[ll*4+1];
    const float bb2 = b_ih[ll*4+2] + b_hh[ll*4+2];
    const float bb3 = b_ih[ll*4+3] + b_hh[ll*4+3];

    // Folded gate coefficients: 0.5x for sigmoid gates (tanh identity), 1x for g
    const float A0 = 0.5f * w_ih[ll*4+0], B0 = 0.5f * w_hh[ll*4+0], C0 = 0.5f * bb0;
    const float A1 = 0.5f * w_ih[ll*4+1], B1 = 0.5f * w_hh[ll*4+1], C1 = 0.5f * bb1;
    const float A2 =        w_ih[ll*4+2], B2 =        w_hh[ll*4+2], C2 =        bb2;
    const float A3 = 0.5f * w_ih[ll*4+3], B3 = 0.5f * w_hh[ll*4+3], C3 = 0.5f * bb3;

    // Half-recurrent weights for the Bog fold: Bog_k = fma(th3, Bh_k, Bh_k)
    const float Bh0 = 0.5f * B0, Bh1 = 0.5f * B1, Bh2 = 0.5f * B2, Bh3 = 0.5f * B3;

    float h = h0[ll];
    float c = c0[ll];

    // Extra state maintained for the fast-path transition
    float thc = 0.0f, ogr = 1.0f;

    float inp_use = 0.0f, inp_buf = 0.0f;
    int t = -2 * ll;   // per-lane timestep counter (guarded steps only)

    // ---------------- guarded step (prologue/epilogue only) ----------------
#define STEP_G(XV)                                                             \
    {                                                                          \
        float inp = (lane == 0) ? (XV) : inp_use;                              \
        float u0 = fmaf(B0, h, fmaf(A0, inp, C0));                             \
        float u1 = fmaf(B1, h, fmaf(A1, inp, C1));                             \
        float u2 = fmaf(B2, h, fmaf(A2, inp, C2));                             \
        float u3 = fmaf(B3, h, fmaf(A3, inp, C3));                             \
        float th0 = fast_tanh(u0);                                             \
        float th1 = fast_tanh(u1);                                             \
        float gg  = fast_tanh(u2);                                             \
        float th3 = fast_tanh(u3);                                             \
        float ig = fmaf(th0, 0.5f, 0.5f);                                      \
        float fg = fmaf(th1, 0.5f, 0.5f);                                      \
        float og = fmaf(th3, 0.5f, 0.5f);                                      \
        float cn = fmaf(fg, c, ig * gg);                                       \
        float tcn = fast_tanh(cn);                                             \
        float hn = og * tcn;                                                   \
        bool ok = ((unsigned)t) < (unsigned)kT;                                \
        h   = ok ? hn  : h;                                                    \
        c   = ok ? cn  : c;                                                    \
        thc = ok ? tcn : thc;                                                  \
        ogr = ok ? og  : ogr;                                                  \
        if (lane == 2 && ok) g_outs[t] = hn;                                   \
        inp_use = inp_buf;                                                     \
        inp_buf = __shfl_up_sync(0xFFFFFFFFu, h, 1);                           \
        t++;                                                                   \
    }

    // -------- fast step (steady state): thc-recurrence, no guards -----------
#define STEP_F(XV, SV)                                                         \
    {                                                                          \
        float inp = (lane == 0) ? (XV) : inp_use;                              \
        float u0 = fmaf(Bog0, thc, fmaf(A0, inp, C0));                         \
        float u2 = fmaf(Bog2, thc, fmaf(A2, inp, C2));                         \
        float u1 = fmaf(Bog1, thc, fmaf(A1, inp, C1));                         \
        float u3 = fmaf(Bog3, thc, fmaf(A3, inp, C3));                         \
        float th0 = fast_tanh(u0);                                             \
        float th2 = fast_tanh(u2);                                             \
        float th1 = fast_tanh(u1);                                             \
        float th3 = fast_tanh(u3);                                             \
        float ig  = fmaf(th0, 0.5f, 0.5f);                                     \
        float igg = ig * th2;                                                  \
        float s   = hc + igg;                                                  \
        float cn  = fmaf(th1, hc, s);                                          \
        float tcn = fast_tanh(cn);                                             \
        Bog0 = fmaf(th3, Bh0, Bh0);                                            \
        Bog1 = fmaf(th3, Bh1, Bh1);                                            \
        Bog2 = fmaf(th3, Bh2, Bh2);                                            \
        Bog3 = fmaf(th3, Bh3, Bh3);                                            \
        float og = fmaf(th3, 0.5f, 0.5f);                                      \
        c   = cn;                                                              \
        hc  = 0.5f * cn;                                                       \
        thc = tcn;                                                             \
        h   = og * tcn;                                                        \
        SV  = h;                                                               \
        inp_use = inp_buf;                                                     \
        inp_buf = __shfl_up_sync(0xFFFFFFFFu, h, 1);                           \
    }

    // Prologue: global steps 0..15 (guarded; lanes 1/2 warm up)
    {
        float p[16];
        #pragma unroll
        for (int j = 0; j < 16; j++) p[j] = 0.0f;
        if (lane == 0) {
            #pragma unroll
            for (int j = 0; j < 4; j++) {
                float4 v = *reinterpret_cast<const float4*>(x + 4*j);
                p[4*j+0]=v.x; p[4*j+1]=v.y; p[4*j+2]=v.z; p[4*j+3]=v.w;
            }
        }
        STEP_G(p[0])  STEP_G(p[1])  STEP_G(p[2])  STEP_G(p[3])
        STEP_G(p[4])  STEP_G(p[5])  STEP_G(p[6])  STEP_G(p[7])
        STEP_G(p[8])  STEP_G(p[9])  STEP_G(p[10]) STEP_G(p[11])
        STEP_G(p[12]) STEP_G(p[13]) STEP_G(p[14]) STEP_G(p[15])
    }

    // Transition to fast-path state
    float hc   = 0.5f * c;
    float Bog0 = B0 * ogr, Bog1 = B1 * ogr, Bog2 = B2 * ogr, Bog3 = B3 * ogr;

    // x queue: q holds x[i .. i+15] at the top of each main block
    float q[16];
    #pragma unroll
    for (int j = 0; j < 16; j++) q[j] = 0.0f;
    if (lane == 0) {
        #pragma unroll
        for (int j = 0; j < 4; j++) {
            float4 v = *reinterpret_cast<const float4*>(x + 16 + 4*j);
            q[4*j+0]=v.x; q[4*j+1]=v.y; q[4*j+2]=v.z; q[4*j+3]=v.w;
        }
    }

    float sv0, sv1, sv2, sv3;

    // Main: global steps 16 .. 32767, 16 steps/block, guard-free.
    // Lane 2 (layer 2) at global step i runs timestep i-4.
    for (int i = 16; i < kT; i += 16) {
        float nx[16];
        #pragma unroll
        for (int j = 0; j < 16; j++) nx[j] = 0.0f;
        if (lane == 0 && (i + 32) <= kT) {
            #pragma unroll
            for (int j = 0; j < 4; j++) {
                float4 v = *reinterpret_cast<const float4*>(x + i + 16 + 4*j);
                nx[4*j+0]=v.x; nx[4*j+1]=v.y; nx[4*j+2]=v.z; nx[4*j+3]=v.w;
            }
        }

        STEP_F(q[0],  sv0) STEP_F(q[1],  sv1) STEP_F(q[2],  sv2) STEP_F(q[3],  sv3)
        if (lane == 2)
            *reinterpret_cast<float4*>(g_outs + i - 4) = make_float4(sv0, sv1, sv2, sv3);
        STEP_F(q[4],  sv0) STEP_F(q[5],  sv1) STEP_F(q[6],  sv2) STEP_F(q[7],  sv3)
        if (lane == 2)
            *reinterpret_cast<float4*>(g_outs + i)     = make_float4(sv0, sv1, sv2, sv3);
        STEP_F(q[8],  sv0) STEP_F(q[9],  sv1) STEP_F(q[10], sv2) STEP_F(q[11], sv3)
        if (lane == 2)
            *reinterpret_cast<float4*>(g_outs + i + 4) = make_float4(sv0, sv1, sv2, sv3);
        STEP_F(q[12], sv0) STEP_F(q[13], sv1) STEP_F(q[14], sv2) STEP_F(q[15], sv3)
        if (lane == 2)
            *reinterpret_cast<float4*>(g_outs + i + 8) = make_float4(sv0, sv1, sv2, sv3);

        #pragma unroll
        for (int j = 0; j < 16; j++) q[j] = nx[j];
    }

    // Epilogue: 4 guarded steps to drain lanes 1 and 2 (lane2 t: 32764..32767)
    t = kT - 2 * ll;
    STEP_G(0.0f) STEP_G(0.0f) STEP_G(0.0f) STEP_G(0.0f)

#undef STEP_G
#undef STEP_F
}

// ---------------------------------------------------------------------------
// GEMV: logits[c] = dot(g_outs, lin_w[c,:]) + lin_b[c]   (HBM-bound, 128 MB)
// ---------------------------------------------------------------------------
__global__ void __launch_bounds__(256)
gemv_kernel(const float* __restrict__ W, const float* __restrict__ lb)
{
    __shared__ float red[256];
    const int c = blockIdx.x;
    const float4* w4 = reinterpret_cast<const float4*>(W + (size_t)c * kT);
    const float4* o4 = reinterpret_cast<const float4*>(g_outs);

    float acc = 0.0f;
    #pragma unroll 4
    for (int j = threadIdx.x; j < kT / 4; j += 256) {
        float4 w = w4[j];
        float4 o = o4[j];
        acc += w.x * o.x + w.y * o.y + w.z * o.z + w.w * o.w;
    }
    red[threadIdx.x] = acc;
    __syncthreads();
    #pragma unroll
    for (int s = 128; s > 0; s >>= 1) {
        if (threadIdx.x < s) red[threadIdx.x] += red[threadIdx.x + s];
        __syncthreads();
    }
    if (threadIdx.x == 0) g_logits[c] = red[0] + lb[c];
}

// ---------------------------------------------------------------------------
// Softmax over 1024 logits, single block.
// ---------------------------------------------------------------------------
__global__ void __launch_bounds__(kCLS)
softmax_kernel(float* __restrict__ out)
{
    __shared__ float sh[kCLS];
    const int i = threadIdx.x;
    float v = g_logits[i];

    sh[i] = v;
    __syncthreads();
    #pragma unroll
    for (int s = kCLS / 2; s > 0; s >>= 1) {
        if (i < s) sh[i] = fmaxf(sh[i], sh[i + s]);
        __syncthreads();
    }
    float m = sh[0];
    __syncthreads();

    float e = expf(v - m);
    sh[i] = e;
    __syncthreads();
    #pragma unroll
    for (int s = kCLS / 2; s > 0; s >>= 1) {
        if (i < s) sh[i] += sh[i + s];
        __syncthreads();
    }
    out[i] = e / sh[0];
}

// ---------------------------------------------------------------------------
// Launch
// ---------------------------------------------------------------------------
extern "C" void kernel_launch(void* const* d_in, const int* in_sizes, int n_in,
                              void* d_out, int out_size)
{
    const float* x     = (const float*)d_in[0];
    const float* h0    = (const float*)d_in[1];
    const float* c0    = (const float*)d_in[2];
    const float* w_ih  = (const float*)d_in[3];
    const float* w_hh  = (const float*)d_in[4];
    const float* b_ih  = (const float*)d_in[5];
    const float* b_hh  = (const float*)d_in[6];
    const float* lin_w = (const float*)d_in[7];
    const float* lin_b = (const float*)d_in[8];

    lstm_kernel<<<1, 32>>>(x, h0, c0, w_ih, w_hh, b_ih, b_hh);
    gemv_kernel<<<kCLS, 256>>>(lin_w, lin_b);
    softmax_kernel<<<1, kCLS>>>((float*)d_out);
}

// round 6
// speedup vs baseline: 1.0178x; 1.0178x over previous
#include <cuda_runtime.h>
#include <cuda_bf16.h>

// Problem constants
#define kT   32768
#define kL   3
#define kCLS 1024

// Scratch (no cudaMalloc allowed) — device globals
__device__ float g_outs[kT];      // top-layer hidden states
__device__ float g_logits[kCLS];  // pre-softmax logits

// Hardware MUFU.TANH — measured (R2/R3) to contribute <1e-6 rel err over the
// full 32768-step recurrence.
__device__ __forceinline__ float fast_tanh(float x) {
    float y; asm("tanh.approx.f32 %0, %1;" : "=f"(y) : "f"(x)); return y;
}

// ---------------------------------------------------------------------------
// LSTM wavefront kernel: 1 warp. Lane l (l<3) runs layer l at timestep
// t = iter - 2*l (lag-2 pipeline: the 26-cycle SHFL cross-layer edge gets a
// full iteration of slack and never binds the recurrence cycle).
//
// Fast step (h-recurrence, hc = 0.5*c):
//   u_k = B_k*h + (A_k*inp + C_k)        pre-terms off-path (inp known early)
//   TANH issue order th0, th2, th1, th3  (cn inputs finish first)
//   ig  = 0.5*th0+0.5 ; igg = ig*th2 ; s = hc+igg
//   cn  = th1*hc + s                     ( == fg*c + ig*gg )
//   tcn = tanh(cn);  og = 0.5*th3+0.5;  h = og*tcn;  hc = 0.5*cn
// In-order dep period ~60 cyc; MUFU pressure 5*8=40 (non-binding).
// ---------------------------------------------------------------------------
__global__ void __launch_bounds__(32, 1)
lstm_kernel(const float* __restrict__ x,
            const float* __restrict__ h0,
            const float* __restrict__ c0,
            const float* __restrict__ w_ih,
            const float* __restrict__ w_hh,
            const float* __restrict__ b_ih,
            const float* __restrict__ b_hh)
{
    const int lane = threadIdx.x & 31;
    const int ll   = (lane < kL) ? lane : (kL - 1);

    const float bb0 = b_ih[ll*4+0] + b_hh[ll*4+0];
    const float bb1 = b_ih[ll*4+1] + b_hh[ll*4+1];
    const float bb2 = b_ih[ll*4+2] + b_hh[ll*4+2];
    const float bb3 = b_ih[ll*4+3] + b_hh[ll*4+3];

    // Folded gate coefficients: 0.5x for sigmoid gates (tanh identity), 1x for g
    const float A0 = 0.5f * w_ih[ll*4+0], B0 = 0.5f * w_hh[ll*4+0], C0 = 0.5f * bb0;
    const float A1 = 0.5f * w_ih[ll*4+1], B1 = 0.5f * w_hh[ll*4+1], C1 = 0.5f * bb1;
    const float A2 =        w_ih[ll*4+2], B2 =        w_hh[ll*4+2], C2 =        bb2;
    const float A3 = 0.5f * w_ih[ll*4+3], B3 = 0.5f * w_hh[ll*4+3], C3 = 0.5f * bb3;

    float h = h0[ll];
    float c = c0[ll];

    float inp_use = 0.0f, inp_buf = 0.0f;
    int t = -2 * ll;   // per-lane timestep counter (guarded steps only)

    // ---------------- guarded step (prologue/epilogue only) ----------------
#define STEP_G(XV)                                                             \
    {                                                                          \
        float inp = (lane == 0) ? (XV) : inp_use;                              \
        float u0 = fmaf(B0, h, fmaf(A0, inp, C0));                             \
        float u1 = fmaf(B1, h, fmaf(A1, inp, C1));                             \
        float u2 = fmaf(B2, h, fmaf(A2, inp, C2));                             \
        float u3 = fmaf(B3, h, fmaf(A3, inp, C3));                             \
        float th0 = fast_tanh(u0);                                             \
        float th1 = fast_tanh(u1);                                             \
        float gg  = fast_tanh(u2);                                             \
        float th3 = fast_tanh(u3);                                             \
        float ig = fmaf(th0, 0.5f, 0.5f);                                      \
        float fg = fmaf(th1, 0.5f, 0.5f);                                      \
        float og = fmaf(th3, 0.5f, 0.5f);                                      \
        float cn = fmaf(fg, c, ig * gg);                                       \
        float hn = og * fast_tanh(cn);                                         \
        bool ok = ((unsigned)t) < (unsigned)kT;                                \
        h = ok ? hn : h;                                                       \
        c = ok ? cn : c;                                                       \
        if (lane == 2 && ok) g_outs[t] = hn;                                   \
        inp_use = inp_buf;                                                     \
        inp_buf = __shfl_up_sync(0xFFFFFFFFu, h, 1);                           \
        t++;                                                                   \
    }

    // -------- fast step (steady state): no guards, hc = 0.5*c --------------
#define STEP_F(XV, SV)                                                         \
    {                                                                          \
        float inp = (lane == 0) ? (XV) : inp_use;                              \
        float u0 = fmaf(B0, h, fmaf(A0, inp, C0));                             \
        float u2 = fmaf(B2, h, fmaf(A2, inp, C2));                             \
        float u1 = fmaf(B1, h, fmaf(A1, inp, C1));                             \
        float u3 = fmaf(B3, h, fmaf(A3, inp, C3));                             \
        float th0 = fast_tanh(u0);                                             \
        float th2 = fast_tanh(u2);                                             \
        float th1 = fast_tanh(u1);                                             \
        float th3 = fast_tanh(u3);                                             \
        float ig  = fmaf(th0, 0.5f, 0.5f);                                     \
        float igg = ig * th2;                                                  \
        float s   = hc + igg;                                                  \
        float cn  = fmaf(th1, hc, s);                                          \
        float tcn = fast_tanh(cn);                                             \
        float og  = fmaf(th3, 0.5f, 0.5f);                                     \
        hc = 0.5f * cn;                                                        \
        h  = og * tcn;                                                         \
        SV = h;                                                                \
        inp_use = inp_buf;                                                     \
        inp_buf = __shfl_up_sync(0xFFFFFFFFu, h, 1);                           \
    }

    // Prologue: global steps 0..15 (guarded; lanes 1/2 warm up)
    {
        float p[16];
        #pragma unroll
        for (int j = 0; j < 16; j++) p[j] = 0.0f;
        if (lane == 0) {
            #pragma unroll
            for (int j = 0; j < 4; j++) {
                float4 v = *reinterpret_cast<const float4*>(x + 4*j);
                p[4*j+0]=v.x; p[4*j+1]=v.y; p[4*j+2]=v.z; p[4*j+3]=v.w;
            }
        }
        STEP_G(p[0])  STEP_G(p[1])  STEP_G(p[2])  STEP_G(p[3])
        STEP_G(p[4])  STEP_G(p[5])  STEP_G(p[6])  STEP_G(p[7])
        STEP_G(p[8])  STEP_G(p[9])  STEP_G(p[10]) STEP_G(p[11])
        STEP_G(p[12]) STEP_G(p[13]) STEP_G(p[14]) STEP_G(p[15])
    }

    // Transition to fast-path state
    float hc = 0.5f * c;

    // x queue: q holds x[i .. i+15] at the top of each main block
    float q[16];
    #pragma unroll
    for (int j = 0; j < 16; j++) q[j] = 0.0f;
    if (lane == 0) {
        #pragma unroll
        for (int j = 0; j < 4; j++) {
            float4 v = *reinterpret_cast<const float4*>(x + 16 + 4*j);
            q[4*j+0]=v.x; q[4*j+1]=v.y; q[4*j+2]=v.z; q[4*j+3]=v.w;
        }
    }

    float sv0, sv1, sv2, sv3;

    // Main: global steps 16 .. 32767, 16 steps/block, guard-free.
    // Lane 2 (layer 2) at global step i runs timestep i-4.
    for (int i = 16; i < kT; i += 16) {
        float nx[16];
        #pragma unroll
        for (int j = 0; j < 16; j++) nx[j] = 0.0f;
        if (lane == 0 && (i + 32) <= kT) {
            #pragma unroll
            for (int j = 0; j < 4; j++) {
                float4 v = *reinterpret_cast<const float4*>(x + i + 16 + 4*j);
                nx[4*j+0]=v.x; nx[4*j+1]=v.y; nx[4*j+2]=v.z; nx[4*j+3]=v.w;
            }
        }

        STEP_F(q[0],  sv0) STEP_F(q[1],  sv1) STEP_F(q[2],  sv2) STEP_F(q[3],  sv3)
        if (lane == 2)
            *reinterpret_cast<float4*>(g_outs + i - 4) = make_float4(sv0, sv1, sv2, sv3);
        STEP_F(q[4],  sv0) STEP_F(q[5],  sv1) STEP_F(q[6],  sv2) STEP_F(q[7],  sv3)
        if (lane == 2)
            *reinterpret_cast<float4*>(g_outs + i)     = make_float4(sv0, sv1, sv2, sv3);
        STEP_F(q[8],  sv0) STEP_F(q[9],  sv1) STEP_F(q[10], sv2) STEP_F(q[11], sv3)
        if (lane == 2)
            *reinterpret_cast<float4*>(g_outs + i + 4) = make_float4(sv0, sv1, sv2, sv3);
        STEP_F(q[12], sv0) STEP_F(q[13], sv1) STEP_F(q[14], sv2) STEP_F(q[15], sv3)
        if (lane == 2)
            *reinterpret_cast<float4*>(g_outs + i + 8) = make_float4(sv0, sv1, sv2, sv3);

        #pragma unroll
        for (int j = 0; j < 16; j++) q[j] = nx[j];
    }

    // Epilogue: restore c, then 4 guarded steps drain lanes 1/2 (t 32764..32767)
    c = hc + hc;
    t = kT - 2 * ll;
    STEP_G(0.0f) STEP_G(0.0f) STEP_G(0.0f) STEP_G(0.0f)

#undef STEP_G
#undef STEP_F
}

// ---------------------------------------------------------------------------
// GEMV: logits[c] = dot(g_outs, lin_w[c,:]) + lin_b[c]   (HBM-bound, 128 MB)
// ---------------------------------------------------------------------------
__global__ void __launch_bounds__(256)
gemv_kernel(const float* __restrict__ W, const float* __restrict__ lb)
{
    __shared__ float red[256];
    const int c = blockIdx.x;
    const float4* w4 = reinterpret_cast<const float4*>(W + (size_t)c * kT);
    const float4* o4 = reinterpret_cast<const float4*>(g_outs);

    float acc = 0.0f;
    #pragma unroll 4
    for (int j = threadIdx.x; j < kT / 4; j += 256) {
        float4 w = w4[j];
        float4 o = o4[j];
        acc += w.x * o.x + w.y * o.y + w.z * o.z + w.w * o.w;
    }
    red[threadIdx.x] = acc;
    __syncthreads();
    #pragma unroll
    for (int s = 128; s > 0; s >>= 1) {
        if (threadIdx.x < s) red[threadIdx.x] += red[threadIdx.x + s];
        __syncthreads();
    }
    if (threadIdx.x == 0) g_logits[c] = red[0] + lb[c];
}

// ---------------------------------------------------------------------------
// Softmax over 1024 logits, single block.
// ---------------------------------------------------------------------------
__global__ void __launch_bounds__(kCLS)
softmax_kernel(float* __restrict__ out)
{
    __shared__ float sh[kCLS];
    const int i = threadIdx.x;
    float v = g_logits[i];

    sh[i] = v;
    __syncthreads();
    #pragma unroll
    for (int s = kCLS / 2; s > 0; s >>= 1) {
        if (i < s) sh[i] = fmaxf(sh[i], sh[i + s]);
        __syncthreads();
    }
    float m = sh[0];
    __syncthreads();

    float e = expf(v - m);
    sh[i] = e;
    __syncthreads();
    #pragma unroll
    for (int s = kCLS / 2; s > 0; s >>= 1) {
        if (i < s) sh[i] += sh[i + s];
        __syncthreads();
    }
    out[i] = e / sh[0];
}

// ---------------------------------------------------------------------------
// Launch
// ---------------------------------------------------------------------------
extern "C" void kernel_launch(void* const* d_in, const int* in_sizes, int n_in,
                              void* d_out, int out_size)
{
    const float* x     = (const float*)d_in[0];
    const float* h0    = (const float*)d_in[1];
    const float* c0    = (const float*)d_in[2];
    const float* w_ih  = (const float*)d_in[3];
    const float* w_hh  = (const float*)d_in[4];
    const float* b_ih  = (const float*)d_in[5];
    const float* b_hh  = (const float*)d_in[6];
    const float* lin_w = (const float*)d_in[7];
    const float* lin_b = (const float*)d_in[8];

    lstm_kernel<<<1, 32>>>(x, h0, c0, w_ih, w_hh, b_ih, b_hh);
    gemv_kernel<<<kCLS, 256>>>(lin_w, lin_b);
    softmax_kernel<<<1, kCLS>>>((float*)d_out);
}

// round 7
// speedup vs baseline: 1.1005x; 1.0813x over previous
#include <cuda_runtime.h>
#include <cuda_bf16.h>

// Problem constants
#define kT   32768
#define kL   3
#define kCLS 1024

// Scratch (no cudaMalloc allowed) — device globals
__device__ float g_outs[kT];      // top-layer hidden states
__device__ float g_logits[kCLS];  // pre-softmax logits

// Hardware MUFU.TANH — measured (R2/R3) to contribute <1e-6 rel err over the
// full 32768-step recurrence.
__device__ __forceinline__ float fast_tanh(float x) {
    float y; asm("tanh.approx.f32 %0, %1;" : "=f"(y) : "f"(x)); return y;
}

// ---------------------------------------------------------------------------
// LSTM wavefront kernel: 1 warp. Lane l (l<3) runs layer l at timestep
// t = iter - 2*l (lag-2 pipeline: the 26-cycle SHFL cross-layer edge gets a
// full iteration of slack and never binds the recurrence cycle).
//
// R6 = R3 structure (8-step blocks, per-step store, low regs) with ONLY the
// STEP_F arithmetic changed:
//   hc = 0.5*c;  cn = th1*hc + (hc + ig*th2)   ( == fg*c + ig*gg )
//   TANH issue order th0, th2, th1, th3 (cn operands first, og off-path)
// ---------------------------------------------------------------------------
__global__ void __launch_bounds__(32, 1)
lstm_kernel(const float* __restrict__ x,
            const float* __restrict__ h0,
            const float* __restrict__ c0,
            const float* __restrict__ w_ih,
            const float* __restrict__ w_hh,
            const float* __restrict__ b_ih,
            const float* __restrict__ b_hh)
{
    const int lane = threadIdx.x & 31;
    const int ll   = (lane < kL) ? lane : (kL - 1);

    const float bb0 = b_ih[ll*4+0] + b_hh[ll*4+0];
    const float bb1 = b_ih[ll*4+1] + b_hh[ll*4+1];
    const float bb2 = b_ih[ll*4+2] + b_hh[ll*4+2];
    const float bb3 = b_ih[ll*4+3] + b_hh[ll*4+3];

    // Folded gate coefficients: 0.5x for sigmoid gates (tanh identity), 1x for g
    const float A0 = 0.5f * w_ih[ll*4+0], B0 = 0.5f * w_hh[ll*4+0], C0 = 0.5f * bb0;
    const float A1 = 0.5f * w_ih[ll*4+1], B1 = 0.5f * w_hh[ll*4+1], C1 = 0.5f * bb1;
    const float A2 =        w_ih[ll*4+2], B2 =        w_hh[ll*4+2], C2 =        bb2;
    const float A3 = 0.5f * w_ih[ll*4+3], B3 = 0.5f * w_hh[ll*4+3], C3 = 0.5f * bb3;

    float h = h0[ll];
    float c = c0[ll];

    float inp_use = 0.0f, inp_buf = 0.0f;
    int t = -2 * ll;   // per-lane timestep counter (guarded steps only)

    // ---------------- guarded step (prologue/epilogue only) ----------------
#define STEP_G(XV)                                                             \
    {                                                                          \
        float inp = (lane == 0) ? (XV) : inp_use;                              \
        float u0 = fmaf(B0, h, fmaf(A0, inp, C0));                             \
        float u1 = fmaf(B1, h, fmaf(A1, inp, C1));                             \
        float u2 = fmaf(B2, h, fmaf(A2, inp, C2));                             \
        float u3 = fmaf(B3, h, fmaf(A3, inp, C3));                             \
        float th0 = fast_tanh(u0);                                             \
        float th1 = fast_tanh(u1);                                             \
        float gg  = fast_tanh(u2);                                             \
        float th3 = fast_tanh(u3);                                             \
        float ig = fmaf(th0, 0.5f, 0.5f);                                      \
        float fg = fmaf(th1, 0.5f, 0.5f);                                      \
        float og = fmaf(th3, 0.5f, 0.5f);                                      \
        float cn = fmaf(fg, c, ig * gg);                                       \
        float hn = og * fast_tanh(cn);                                         \
        bool ok = ((unsigned)t) < (unsigned)kT;                                \
        h = ok ? hn : h;                                                       \
        c = ok ? cn : c;                                                       \
        if (lane == 2 && ok) g_outs[t] = hn;                                   \
        inp_use = inp_buf;                                                     \
        inp_buf = __shfl_up_sync(0xFFFFFFFFu, h, 1);                           \
        t++;                                                                   \
    }

    // -------- fast step (steady state): no guards, hc = 0.5*c --------------
#define STEP_F(XV, TIDX)                                                       \
    {                                                                          \
        float inp = (lane == 0) ? (XV) : inp_use;                              \
        float u0 = fmaf(B0, h, fmaf(A0, inp, C0));                             \
        float u2 = fmaf(B2, h, fmaf(A2, inp, C2));                             \
        float u1 = fmaf(B1, h, fmaf(A1, inp, C1));                             \
        float u3 = fmaf(B3, h, fmaf(A3, inp, C3));                             \
        float th0 = fast_tanh(u0);                                             \
        float th2 = fast_tanh(u2);                                             \
        float th1 = fast_tanh(u1);                                             \
        float th3 = fast_tanh(u3);                                             \
        float ig  = fmaf(th0, 0.5f, 0.5f);                                     \
        float igg = ig * th2;                                                  \
        float s   = hc + igg;                                                  \
        float cn  = fmaf(th1, hc, s);                                          \
        float tcn = fast_tanh(cn);                                             \
        float og  = fmaf(th3, 0.5f, 0.5f);                                     \
        hc = 0.5f * cn;                                                        \
        h  = og * tcn;                                                         \
        if (lane == 2) g_outs[TIDX] = h;                                       \
        inp_use = inp_buf;                                                     \
        inp_buf = __shfl_up_sync(0xFFFFFFFFu, h, 1);                           \
    }

    // Prologue: global steps 0..7 (guarded; lanes 1/2 warm up)
    {
        float p[8] = {0,0,0,0,0,0,0,0};
        if (lane == 0) {
            float4 a = *reinterpret_cast<const float4*>(x);
            float4 b = *reinterpret_cast<const float4*>(x + 4);
            p[0]=a.x; p[1]=a.y; p[2]=a.z; p[3]=a.w;
            p[4]=b.x; p[5]=b.y; p[6]=b.z; p[7]=b.w;
        }
        STEP_G(p[0]) STEP_G(p[1]) STEP_G(p[2]) STEP_G(p[3])
        STEP_G(p[4]) STEP_G(p[5]) STEP_G(p[6]) STEP_G(p[7])
    }

    // Transition to fast-path state
    float hc = 0.5f * c;

    // Rolling x queue: q holds x[i .. i+15] at the top of each main block.
    float q[16];
    if (lane == 0) {
        #pragma unroll
        for (int j = 0; j < 4; j++) {
            float4 v = *reinterpret_cast<const float4*>(x + 8 + 4*j);
            q[4*j+0]=v.x; q[4*j+1]=v.y; q[4*j+2]=v.z; q[4*j+3]=v.w;
        }
    } else {
        #pragma unroll
        for (int j = 0; j < 16; j++) q[j] = 0.0f;
    }

    // Main: global steps 8 .. 32767, 8 steps/block, guard-free.
    // Lane 2 (layer 2) at global step i runs timestep i-4.
    for (int i = 8; i < kT; i += 8) {
        float nx[8];
        #pragma unroll
        for (int j = 0; j < 8; j++) nx[j] = 0.0f;
        if (lane == 0 && (i + 24) <= kT) {
            float4 a = *reinterpret_cast<const float4*>(x + i + 16);
            float4 b = *reinterpret_cast<const float4*>(x + i + 20);
            nx[0]=a.x; nx[1]=a.y; nx[2]=a.z; nx[3]=a.w;
            nx[4]=b.x; nx[5]=b.y; nx[6]=b.z; nx[7]=b.w;
        }

        STEP_F(q[0], i - 4 + 0) STEP_F(q[1], i - 4 + 1)
        STEP_F(q[2], i - 4 + 2) STEP_F(q[3], i - 4 + 3)
        STEP_F(q[4], i - 4 + 4) STEP_F(q[5], i - 4 + 5)
        STEP_F(q[6], i - 4 + 6) STEP_F(q[7], i - 4 + 7)

        #pragma unroll
        for (int j = 0; j < 8; j++) { q[j] = q[j+8]; q[j+8] = nx[j]; }
    }

    // Epilogue: restore c, then 4 guarded steps drain lanes 1/2 (t 32764..32767)
    c = hc + hc;
    t = kT - 2 * ll;
    STEP_G(0.0f) STEP_G(0.0f) STEP_G(0.0f) STEP_G(0.0f)

#undef STEP_G
#undef STEP_F
}

// ---------------------------------------------------------------------------
// GEMV: logits[c] = dot(g_outs, lin_w[c,:]) + lin_b[c]   (HBM-bound, 128 MB)
// ---------------------------------------------------------------------------
__global__ void __launch_bounds__(256)
gemv_kernel(const float* __restrict__ W, const float* __restrict__ lb)
{
    __shared__ float red[256];
    const int c = blockIdx.x;
    const float4* w4 = reinterpret_cast<const float4*>(W + (size_t)c * kT);
    const float4* o4 = reinterpret_cast<const float4*>(g_outs);

    float acc = 0.0f;
    #pragma unroll 4
    for (int j = threadIdx.x; j < kT / 4; j += 256) {
        float4 w = w4[j];
        float4 o = o4[j];
        acc += w.x * o.x + w.y * o.y + w.z * o.z + w.w * o.w;
    }
    red[threadIdx.x] = acc;
    __syncthreads();
    #pragma unroll
    for (int s = 128; s > 0; s >>= 1) {
        if (threadIdx.x < s) red[threadIdx.x] += red[threadIdx.x + s];
        __syncthreads();
    }
    if (threadIdx.x == 0) g_logits[c] = red[0] + lb[c];
}

// ---------------------------------------------------------------------------
// Softmax over 1024 logits, single block.
// ---------------------------------------------------------------------------
__global__ void __launch_bounds__(kCLS)
softmax_kernel(float* __restrict__ out)
{
    __shared__ float sh[kCLS];
    const int i = threadIdx.x;
    float v = g_logits[i];

    sh[i] = v;
    __syncthreads();
    #pragma unroll
    for (int s = kCLS / 2; s > 0; s >>= 1) {
        if (i < s) sh[i] = fmaxf(sh[i], sh[i + s]);
        __syncthreads();
    }
    float m = sh[0];
    __syncthreads();

    float e = expf(v - m);
    sh[i] = e;
    __syncthreads();
    #pragma unroll
    for (int s = kCLS / 2; s > 0; s >>= 1) {
        if (i < s) sh[i] += sh[i + s];
        __syncthreads();
    }
    out[i] = e / sh[0];
}

// ---------------------------------------------------------------------------
// Launch
// ---------------------------------------------------------------------------
extern "C" void kernel_launch(void* const* d_in, const int* in_sizes, int n_in,
                              void* d_out, int out_size)
{
    const float* x     = (const float*)d_in[0];
    const float* h0    = (const float*)d_in[1];
    const float* c0    = (const float*)d_in[2];
    const float* w_ih  = (const float*)d_in[3];
    const float* w_hh  = (const float*)d_in[4];
    const float* b_ih  = (const float*)d_in[5];
    const float* b_hh  = (const float*)d_in[6];
    const float* lin_w = (const float*)d_in[7];
    const float* lin_b = (const float*)d_in[8];

    lstm_kernel<<<1, 32>>>(x, h0, c0, w_ih, w_hh, b_ih, b_hh);
    gemv_kernel<<<kCLS, 256>>>(lin_w, lin_b);
    softmax_kernel<<<1, kCLS>>>((float*)d_out);
}

// round 8
// speedup vs baseline: 1.1705x; 1.0636x over previous
#include <cuda_runtime.h>
#include <cuda_bf16.h>

// Problem constants
#define kT   32768
#define kL   3
#define kCLS 1024

// Scratch (no cudaMalloc allowed) — device globals
__device__ float g_outs[kT];      // top-layer hidden states
__device__ float g_logits[kCLS];  // pre-softmax logits

// Hardware MUFU.TANH — measured (R2/R3) to contribute <1e-6 rel err over the
// full 32768-step recurrence. Effective latency ~24 cyc (16 + SB overhead).
__device__ __forceinline__ float fast_tanh(float x) {
    float y; asm("tanh.approx.f32 %0, %1;" : "=f"(y) : "f"(x)); return y;
}

// ---------------------------------------------------------------------------
// LSTM wavefront kernel: 1 warp. Lane l (l<3) runs layer l at timestep
// t = iter - 2*l (lag-2 pipeline: the 26-cycle SHFL cross-layer edge gets a
// full iteration of slack and never binds the recurrence cycle).
//
// R7 = R6 with the tcn-recurrence: carry tcn = tanh(c) and Bog_k = B_k*og
// (computed in the tanh(cn) latency shadow), so the next step's gate FMAs
//   u_k' = Bog_k * tcn + pre_k'
// issue the moment tanh(cn) lands — the h' = og*tcn multiply moves off the
// recurrence cycle (needed only for shfl/store).
// ---------------------------------------------------------------------------
__global__ void __launch_bounds__(32, 1)
lstm_kernel(const float* __restrict__ x,
            const float* __restrict__ h0,
            const float* __restrict__ c0,
            const float* __restrict__ w_ih,
            const float* __restrict__ w_hh,
            const float* __restrict__ b_ih,
            const float* __restrict__ b_hh)
{
    const int lane = threadIdx.x & 31;
    const int ll   = (lane < kL) ? lane : (kL - 1);

    const float bb0 = b_ih[ll*4+0] + b_hh[ll*4+0];
    const float bb1 = b_ih[ll*4+1] + b_hh[ll*4+1];
    const float bb2 = b_ih[ll*4+2] + b_hh[ll*4+2];
    const float bb3 = b_ih[ll*4+3] + b_hh[ll*4+3];

    // Folded gate coefficients: 0.5x for sigmoid gates (tanh identity), 1x for g
    const float A0 = 0.5f * w_ih[ll*4+0], B0 = 0.5f * w_hh[ll*4+0], C0 = 0.5f * bb0;
    const float A1 = 0.5f * w_ih[ll*4+1], B1 = 0.5f * w_hh[ll*4+1], C1 = 0.5f * bb1;
    const float A2 =        w_ih[ll*4+2], B2 =        w_hh[ll*4+2], C2 =        bb2;
    const float A3 = 0.5f * w_ih[ll*4+3], B3 = 0.5f * w_hh[ll*4+3], C3 = 0.5f * bb3;

    float h = h0[ll];
    float c = c0[ll];

    // Tracked for the prologue -> fast-path transition
    float thc = 0.0f, ogr = 1.0f;

    float inp_use = 0.0f, inp_buf = 0.0f;
    int t = -2 * ll;   // per-lane timestep counter (guarded steps only)

    // ---------------- guarded step (prologue/epilogue only) ----------------
#define STEP_G(XV)                                                             \
    {                                                                          \
        float inp = (lane == 0) ? (XV) : inp_use;                              \
        float u0 = fmaf(B0, h, fmaf(A0, inp, C0));                             \
        float u1 = fmaf(B1, h, fmaf(A1, inp, C1));                             \
        float u2 = fmaf(B2, h, fmaf(A2, inp, C2));                             \
        float u3 = fmaf(B3, h, fmaf(A3, inp, C3));                             \
        float th0 = fast_tanh(u0);                                             \
        float th1 = fast_tanh(u1);                                             \
        float gg  = fast_tanh(u2);                                             \
        float th3 = fast_tanh(u3);                                             \
        float ig = fmaf(th0, 0.5f, 0.5f);                                      \
        float fg = fmaf(th1, 0.5f, 0.5f);                                      \
        float og = fmaf(th3, 0.5f, 0.5f);                                      \
        float cn = fmaf(fg, c, ig * gg);                                       \
        float tcn = fast_tanh(cn);                                             \
        float hn = og * tcn;                                                   \
        bool ok = ((unsigned)t) < (unsigned)kT;                                \
        h   = ok ? hn  : h;                                                    \
        c   = ok ? cn  : c;                                                    \
        thc = ok ? tcn : thc;                                                  \
        ogr = ok ? og  : ogr;                                                  \
        if (lane == 2 && ok) g_outs[t] = hn;                                   \
        inp_use = inp_buf;                                                     \
        inp_buf = __shfl_up_sync(0xFFFFFFFFu, h, 1);                           \
        t++;                                                                   \
    }

    // -------- fast step (steady state): tcn-recurrence, no guards -----------
#define STEP_F(XV, TIDX)                                                       \
    {                                                                          \
        float inp = (lane == 0) ? (XV) : inp_use;                              \
        float u0 = fmaf(Bog0, tcn, fmaf(A0, inp, C0));                         \
        float u2 = fmaf(Bog2, tcn, fmaf(A2, inp, C2));                         \
        float u1 = fmaf(Bog1, tcn, fmaf(A1, inp, C1));                         \
        float u3 = fmaf(Bog3, tcn, fmaf(A3, inp, C3));                         \
        float th0 = fast_tanh(u0);                                             \
        float th2 = fast_tanh(u2);                                             \
        float th1 = fast_tanh(u1);                                             \
        float th3 = fast_tanh(u3);                                             \
        float ig  = fmaf(th0, 0.5f, 0.5f);                                     \
        float igg = ig * th2;                                                  \
        float s   = hc + igg;                                                  \
        float cn  = fmaf(th1, hc, s);                                          \
        float tnew = fast_tanh(cn);                                            \
        float og  = fmaf(th3, 0.5f, 0.5f);                                     \
        Bog0 = B0 * og;                                                        \
        Bog1 = B1 * og;                                                        \
        Bog2 = B2 * og;                                                        \
        Bog3 = B3 * og;                                                        \
        hc  = 0.5f * cn;                                                       \
        tcn = tnew;                                                            \
        h   = og * tnew;                                                       \
        if (lane == 2) g_outs[TIDX] = h;                                       \
        inp_use = inp_buf;                                                     \
        inp_buf = __shfl_up_sync(0xFFFFFFFFu, h, 1);                           \
    }

    // Prologue: global steps 0..7 (guarded; lanes 1/2 warm up)
    {
        float p[8] = {0,0,0,0,0,0,0,0};
        if (lane == 0) {
            float4 a = *reinterpret_cast<const float4*>(x);
            float4 b = *reinterpret_cast<const float4*>(x + 4);
            p[0]=a.x; p[1]=a.y; p[2]=a.z; p[3]=a.w;
            p[4]=b.x; p[5]=b.y; p[6]=b.z; p[7]=b.w;
        }
        STEP_G(p[0]) STEP_G(p[1]) STEP_G(p[2]) STEP_G(p[3])
        STEP_G(p[4]) STEP_G(p[5]) STEP_G(p[6]) STEP_G(p[7])
    }

    // Transition to fast-path state
    float hc   = 0.5f * c;
    float tcn  = thc;
    float Bog0 = B0 * ogr, Bog1 = B1 * ogr, Bog2 = B2 * ogr, Bog3 = B3 * ogr;

    // Rolling x queue: q holds x[i .. i+15] at the top of each main block.
    float q[16];
    if (lane == 0) {
        #pragma unroll
        for (int j = 0; j < 4; j++) {
            float4 v = *reinterpret_cast<const float4*>(x + 8 + 4*j);
            q[4*j+0]=v.x; q[4*j+1]=v.y; q[4*j+2]=v.z; q[4*j+3]=v.w;
        }
    } else {
        #pragma unroll
        for (int j = 0; j < 16; j++) q[j] = 0.0f;
    }

    // Main: global steps 8 .. 32767, 8 steps/block, guard-free.
    // Lane 2 (layer 2) at global step i runs timestep i-4.
    for (int i = 8; i < kT; i += 8) {
        float nx[8];
        #pragma unroll
        for (int j = 0; j < 8; j++) nx[j] = 0.0f;
        if (lane == 0 && (i + 24) <= kT) {
            float4 a = *reinterpret_cast<const float4*>(x + i + 16);
            float4 b = *reinterpret_cast<const float4*>(x + i + 20);
            nx[0]=a.x; nx[1]=a.y; nx[2]=a.z; nx[3]=a.w;
            nx[4]=b.x; nx[5]=b.y; nx[6]=b.z; nx[7]=b.w;
        }

        STEP_F(q[0], i - 4 + 0) STEP_F(q[1], i - 4 + 1)
        STEP_F(q[2], i - 4 + 2) STEP_F(q[3], i - 4 + 3)
        STEP_F(q[4], i - 4 + 4) STEP_F(q[5], i - 4 + 5)
        STEP_F(q[6], i - 4 + 6) STEP_F(q[7], i - 4 + 7)

        #pragma unroll
        for (int j = 0; j < 8; j++) { q[j] = q[j+8]; q[j+8] = nx[j]; }
    }

    // Epilogue: restore c, then 4 guarded steps drain lanes 1/2 (t 32764..32767)
    c = hc + hc;
    t = kT - 2 * ll;
    STEP_G(0.0f) STEP_G(0.0f) STEP_G(0.0f) STEP_G(0.0f)

#undef STEP_G
#undef STEP_F
}

// ---------------------------------------------------------------------------
// GEMV: logits[c] = dot(g_outs, lin_w[c,:]) + lin_b[c]   (HBM-bound, 128 MB)
// ---------------------------------------------------------------------------
__global__ void __launch_bounds__(256)
gemv_kernel(const float* __restrict__ W, const float* __restrict__ lb)
{
    __shared__ float red[256];
    const int c = blockIdx.x;
    const float4* w4 = reinterpret_cast<const float4*>(W + (size_t)c * kT);
    const float4* o4 = reinterpret_cast<const float4*>(g_outs);

    float acc = 0.0f;
    #pragma unroll 4
    for (int j = threadIdx.x; j < kT / 4; j += 256) {
        float4 w = w4[j];
        float4 o = o4[j];
        acc += w.x * o.x + w.y * o.y + w.z * o.z + w.w * o.w;
    }
    red[threadIdx.x] = acc;
    __syncthreads();
    #pragma unroll
    for (int s = 128; s > 0; s >>= 1) {
        if (threadIdx.x < s) red[threadIdx.x] += red[threadIdx.x + s];
        __syncthreads();
    }
    if (threadIdx.x == 0) g_logits[c] = red[0] + lb[c];
}

// ---------------------------------------------------------------------------
// Softmax over 1024 logits, single block.
// ---------------------------------------------------------------------------
__global__ void __launch_bounds__(kCLS)
softmax_kernel(float* __restrict__ out)
{
    __shared__ float sh[kCLS];
    const int i = threadIdx.x;
    float v = g_logits[i];

    sh[i] = v;
    __syncthreads();
    #pragma unroll
    for (int s = kCLS / 2; s > 0; s >>= 1) {
        if (i < s) sh[i] = fmaxf(sh[i], sh[i + s]);
        __syncthreads();
    }
    float m = sh[0];
    __syncthreads();

    float e = expf(v - m);
    sh[i] = e;
    __syncthreads();
    #pragma unroll
    for (int s = kCLS / 2; s > 0; s >>= 1) {
        if (i < s) sh[i] += sh[i + s];
        __syncthreads();
    }
    out[i] = e / sh[0];
}

// ---------------------------------------------------------------------------
// Launch
// ---------------------------------------------------------------------------
extern "C" void kernel_launch(void* const* d_in, const int* in_sizes, int n_in,
                              void* d_out, int out_size)
{
    const float* x     = (const float*)d_in[0];
    const float* h0    = (const float*)d_in[1];
    const float* c0    = (const float*)d_in[2];
    const float* w_ih  = (const float*)d_in[3];
    const float* w_hh  = (const float*)d_in[4];
    const float* b_ih  = (const float*)d_in[5];
    const float* b_hh  = (const float*)d_in[6];
    const float* lin_w = (const float*)d_in[7];
    const float* lin_b = (const float*)d_in[8];

    lstm_kernel<<<1, 32>>>(x, h0, c0, w_ih, w_hh, b_ih, b_hh);
    gemv_kernel<<<kCLS, 256>>>(lin_w, lin_b);
    softmax_kernel<<<1, kCLS>>>((float*)d_out);
}